// round 15
// baseline (speedup 1.0000x reference)
#include <cuda_runtime.h>

#define NN 100000
#define NE 1600000
#define CH 64
#define NG 64
#define SCAN_BS 1024
#define SCAN_NB ((NN + SCAN_BS - 1) / SCAN_BS)   // 98
#define TILE_N 128                                // nodes per node-kernel block

// ---------------- device scratch (no allocation allowed) ----------------
__device__ __align__(16) float g_agg[NN * CH];
__device__ __align__(16) float g_h0[NN * CH];
__device__ __align__(16) float g_h1[NN * CH];
__device__ float g_inv[NN];
__device__ int   g_deg[NN];
__device__ int   g_off[NN];
__device__ int   g_fill[NN];
__device__ int   g_srcl[NE];
__device__ float g_pool[NG * CH];
__device__ float g_pcnt[NG];
__device__ int   g_is64_ei;
__device__ int   g_is64_b;
// lookback-scan + pool-completion bookkeeping
__device__ int   g_ticket;
__device__ int   g_status[SCAN_NB];   // 0=invalid, 1=aggregate ready, 2=prefix ready
__device__ int   g_aggv[SCAN_NB];
__device__ int   g_prefv[SCAN_NB];
__device__ int   g_pool_done;

__device__ __forceinline__ unsigned to_tf32(float f) {
    unsigned r;
    asm("cvt.rna.tf32.f32 %0, %1;" : "=r"(r) : "f"(f));
    return r;
}

// ---------------- init: zero deg/pool/bookkeeping + dtype detect ----------------
// int64 little-endian with values < 2^31 => odd 32-bit words are zero.
// Probe indices are in-bounds for BOTH int32 and int64 layouts.
__global__ void init_kernel(const int* __restrict__ ei32, const int* __restrict__ b32) {
    int i = blockIdx.x * blockDim.x + threadIdx.x;
    if (i < NN) g_deg[i] = 0;
    if (blockIdx.x == 0) {
        for (int j = threadIdx.x; j < NG * CH; j += blockDim.x) g_pool[j] = 0.f;
        if (threadIdx.x < NG) g_pcnt[threadIdx.x] = 0.f;
        if (threadIdx.x < SCAN_NB) g_status[threadIdx.x] = 0;
        if (threadIdx.x == 0) {
            g_ticket = 0;
            g_pool_done = 0;
            int oe = 0, ob = 0;
#pragma unroll 1
            for (int t = 0; t < 64; t++) oe |= ei32[2 * (t * 24999 + 7) + 1];
#pragma unroll 1
            for (int t = 0; t < 64; t++) ob |= b32[2 * (t * 780 + 3) + 1];
            g_is64_ei = (oe == 0) ? 1 : 0;
            g_is64_b  = (ob == 0) ? 1 : 0;
        }
    }
}

// ---------------- CSR build ----------------
__global__ void deg_kernel(const int* __restrict__ ei) {
    int e = blockIdx.x * blockDim.x + threadIdx.x;
    if (e < NE) {
        int d = g_is64_ei ? ei[2 * (NE + e)] : ei[NE + e];
        atomicAdd(&g_deg[d], 1);
    }
}

// single-pass decoupled-lookback exclusive scan of g_deg -> g_off (+ fill-cursor + inv)
__global__ void scan_kernel() {
    __shared__ int s[SCAN_BS];
    __shared__ int sh_bid;
    __shared__ int sh_base;
    int t = threadIdx.x;

    if (t == 0) sh_bid = atomicAdd(&g_ticket, 1);
    __syncthreads();
    int bid = sh_bid;

    int gid = bid * SCAN_BS + t;
    int v = (gid < NN) ? g_deg[gid] : 0;
    s[t] = v;
    __syncthreads();
    for (int off = 1; off < SCAN_BS; off <<= 1) {
        int x = (t >= off) ? s[t - off] : 0;
        __syncthreads();
        s[t] += x;
        __syncthreads();
    }
    int total = s[SCAN_BS - 1];

    if (t == 0) {
        if (bid == 0) {
            g_prefv[0] = total;
            __threadfence();
            ((volatile int*)g_status)[0] = 2;
            sh_base = 0;
        } else {
            g_aggv[bid] = total;
            __threadfence();
            ((volatile int*)g_status)[bid] = 1;
            // lookback
            int base = 0;
            int p = bid - 1;
            while (p >= 0) {
                int st;
                do { st = ((volatile int*)g_status)[p]; } while (st == 0);
                __threadfence();
                if (st == 2) { base += g_prefv[p]; break; }
                base += g_aggv[p];
                p--;
            }
            g_prefv[bid] = base + total;
            __threadfence();
            ((volatile int*)g_status)[bid] = 2;
            sh_base = base;
        }
    }
    __syncthreads();
    int base = sh_base;

    if (gid < NN) {
        int o = base + s[t] - v;     // exclusive prefix
        g_off[gid]  = o;
        g_fill[gid] = o;
        g_inv[gid]  = 1.0f / fmaxf((float)g_deg[gid], 1.0f);
    }
}

__global__ void fill_kernel(const int* __restrict__ ei) {
    int e = blockIdx.x * blockDim.x + threadIdx.x;
    if (e < NE) {
        int is64 = g_is64_ei;
        int s = is64 ? ei[2 * e]        : ei[e];
        int d = is64 ? ei[2 * (NE + e)] : ei[NE + e];
        g_srcl[atomicAdd(&g_fill[d], 1)] = s;
    }
}

// ---------------- aggregation via gather (R13-proven: LDG.64 lanes + 4-edge unroll) ----------------
__global__ void __launch_bounds__(256) gather_kernel(const float* __restrict__ Xext,
                                                     int srcsel) {
    const float* __restrict__ X = (srcsel == 0) ? Xext : (srcsel == 1 ? g_h0 : g_h1);
    int warp = (blockIdx.x * blockDim.x + threadIdx.x) >> 5;
    if (warp >= NN) return;
    int lane = threadIdx.x & 31;
    int co = lane * 2;                 // channel offset for this lane
    int beg = g_off[warp];
    int deg = g_deg[warp];

    float a0 = 0.f, a1 = 0.f;
    int j = 0;
    for (; j + 4 <= deg; j += 4) {
        int s0 = g_srcl[beg + j];
        int s1 = g_srcl[beg + j + 1];
        int s2 = g_srcl[beg + j + 2];
        int s3 = g_srcl[beg + j + 3];
        float2 v0 = *(const float2*)(X + (size_t)s0 * CH + co);
        float2 v1 = *(const float2*)(X + (size_t)s1 * CH + co);
        float2 v2 = *(const float2*)(X + (size_t)s2 * CH + co);
        float2 v3 = *(const float2*)(X + (size_t)s3 * CH + co);
        a0 += v0.x + v1.x + v2.x + v3.x;
        a1 += v0.y + v1.y + v2.y + v3.y;
    }
    for (; j < deg; j++) {
        float2 v = *(const float2*)(X + (size_t)g_srcl[beg + j] * CH + co);
        a0 += v.x;
        a1 += v.y;
    }
    float iv = g_inv[warp];
    *(float2*)(g_agg + (size_t)warp * CH + co) = make_float2(a0 * iv, a1 * iv);
}

// ---------------- node transform: tf32 tensor-core GEMM (R13-proven) ----------------
// Y = relu([agg | X] @ [Wl;Wr] + b) via mma.sync.m16n8k8 tf32.
// 128-node tile, 256 threads (8 warps), warp computes a 16x64 output tile.
__global__ void __launch_bounds__(256) node_kernel(const float* __restrict__ Xext,
                                                   const float* __restrict__ Wl,
                                                   const float* __restrict__ bvec,
                                                   const float* __restrict__ Wr,
                                                   int srcsel, int dstsel) {
    const float* __restrict__ Xin = (srcsel == 0) ? Xext : (srcsel == 1 ? g_h0 : g_h1);
    float* __restrict__ Yout = (dstsel == 1) ? g_h0 : g_h1;

    __shared__ __align__(16) unsigned Wt[64][132];    // 33.8 KB: Wt[n][k], k<64: Wl, else Wr
    __shared__ __align__(16) unsigned As[TILE_N][20]; // 10.2 KB: A chunk [node][16 k]
    __shared__ float bs[64];

    int tid = threadIdx.x;
    int nbase = blockIdx.x * TILE_N;
    int w = tid >> 5;          // warp 0..7: nodes 16w .. 16w+15
    int lane = tid & 31;
    int g = lane >> 2;         // 0..7
    int tq = lane & 3;         // 0..3

    // ---- stage Wt (transposed, tf32) + bias ----
    for (int i = tid; i < 64 * 64; i += 256) {
        int k = i >> 6, n = i & 63;
        Wt[n][k]      = to_tf32(Wl[i]);   // Wl[k][n]
        Wt[n][k + 64] = to_tf32(Wr[i]);
    }
    if (tid < 64) bs[tid] = bvec[tid];

    float acc[8][4];
#pragma unroll
    for (int nt = 0; nt < 8; nt++)
#pragma unroll
        for (int q = 0; q < 4; q++) acc[nt][q] = 0.f;

#pragma unroll 1
    for (int c = 0; c < 8; c++) {            // 8 chunks of 16 k; c<4: agg, else X
        __syncthreads();
        {   // stage A chunk (tf32)
            const float* __restrict__ S = (c < 4) ? g_agg : Xin;
            int koff = (c & 3) * 16;
            int k4 = (tid & 3) * 4;
            int n0 = tid >> 2;               // 0..63
#pragma unroll
            for (int nn = n0; nn < TILE_N; nn += 64) {
                int n = nbase + nn;
                float4 v = make_float4(0.f, 0.f, 0.f, 0.f);
                if (n < NN) v = *(const float4*)&S[(size_t)n * CH + koff + k4];
                As[nn][k4 + 0] = to_tf32(v.x);
                As[nn][k4 + 1] = to_tf32(v.y);
                As[nn][k4 + 2] = to_tf32(v.z);
                As[nn][k4 + 3] = to_tf32(v.w);
            }
        }
        __syncthreads();
        int kb = c * 16;                     // k base within 0..127 (Wt column)
#pragma unroll
        for (int ks = 0; ks < 2; ks++) {     // two k8 steps per chunk
            int kk = ks * 8;
            unsigned a0 = As[w * 16 + g][kk + tq];
            unsigned a1 = As[w * 16 + g + 8][kk + tq];
            unsigned a2 = As[w * 16 + g][kk + tq + 4];
            unsigned a3 = As[w * 16 + g + 8][kk + tq + 4];
#pragma unroll
            for (int nt = 0; nt < 8; nt++) {
                unsigned b0 = Wt[nt * 8 + g][kb + kk + tq];
                unsigned b1 = Wt[nt * 8 + g][kb + kk + tq + 4];
                asm volatile(
                    "mma.sync.aligned.m16n8k8.row.col.f32.tf32.tf32.f32 "
                    "{%0,%1,%2,%3}, {%4,%5,%6,%7}, {%8,%9}, {%0,%1,%2,%3};"
                    : "+f"(acc[nt][0]), "+f"(acc[nt][1]),
                      "+f"(acc[nt][2]), "+f"(acc[nt][3])
                    : "r"(a0), "r"(a1), "r"(a2), "r"(a3), "r"(b0), "r"(b1));
            }
        }
    }

    // ---- epilogue: bias + relu + store ----
    int n0 = nbase + w * 16 + g;
    int n1 = n0 + 8;
#pragma unroll
    for (int nt = 0; nt < 8; nt++) {
        int col = nt * 8 + 2 * tq;
        float b0 = bs[col], b1 = bs[col + 1];
        if (n0 < NN) {
            float2 o = make_float2(fmaxf(acc[nt][0] + b0, 0.f),
                                   fmaxf(acc[nt][1] + b1, 0.f));
            *(float2*)&Yout[(size_t)n0 * CH + col] = o;
        }
        if (n1 < NN) {
            float2 o = make_float2(fmaxf(acc[nt][2] + b0, 0.f),
                                   fmaxf(acc[nt][3] + b1, 0.f));
            *(float2*)&Yout[(size_t)n1 * CH + col] = o;
        }
    }
}

// ---------------- pooling (batch is sorted) + fused MLP head ----------------
// All blocks accumulate pool sums; the LAST block (completion counter) runs the head.
__global__ void __launch_bounds__(256) pool_kernel(const int* __restrict__ batch,
                                                   const float* __restrict__ Wc1,
                                                   const float* __restrict__ bc1,
                                                   const float* __restrict__ Wc2,
                                                   const float* __restrict__ bc2,
                                                   float* __restrict__ out) {
    int is64 = g_is64_b;
    const float* H = g_h0;   // final layer output lives in g_h0
    int c = threadIdx.x & 63;
    int rg = threadIdx.x >> 6;
    int r0 = blockIdx.x * 256 + rg * 64;
    float acc = 0.f, cacc = 0.f;
    int cur = -1;
    for (int i = 0; i < 64; i++) {
        int r = r0 + i;
        if (r >= NN) break;
        int g = is64 ? batch[2 * r] : batch[r];
        if (g != cur) {
            if (cur >= 0) {
                atomicAdd(&g_pool[cur * CH + c], acc);
                if (c == 0) atomicAdd(&g_pcnt[cur], cacc);
            }
            cur = g; acc = 0.f; cacc = 0.f;
        }
        acc += H[(size_t)r * CH + c];
        cacc += 1.f;
    }
    if (cur >= 0) {
        atomicAdd(&g_pool[cur * CH + c], acc);
        if (c == 0) atomicAdd(&g_pcnt[cur], cacc);
    }

    // completion counter: last block runs the head
    __shared__ int sh_last;
    __threadfence();
    __syncthreads();
    if (threadIdx.x == 0) {
        int done = atomicAdd(&g_pool_done, 1);
        sh_last = (done == (int)gridDim.x - 1) ? 1 : 0;
    }
    __syncthreads();
    if (sh_last) {
        __threadfence();
        int g = threadIdx.x;
        if (g < NG) {
            float iv = 1.0f / fmaxf(g_pcnt[g], 1.0f);
            float gv[64];
#pragma unroll
            for (int k = 0; k < 64; k++) gv[k] = g_pool[g * CH + k] * iv;
            float o0 = bc2[0], o1 = bc2[1];
            for (int j = 0; j < 32; j++) {
                float h = bc1[j];
#pragma unroll
                for (int k = 0; k < 64; k++) h += gv[k] * Wc1[k * 32 + j];
                h = fmaxf(h, 0.f);
                o0 += h * Wc2[j * 2 + 0];
                o1 += h * Wc2[j * 2 + 1];
            }
            out[g * 2 + 0] = o0;
            out[g * 2 + 1] = o1;
        }
    }
}

extern "C" void kernel_launch(void* const* d_in, const int* in_sizes, int n_in,
                              void* d_out, int out_size) {
    (void)in_sizes; (void)n_in; (void)out_size;
    const float* x   = (const float*)d_in[0];
    const int* ei    = (const int*)d_in[1];    // width auto-detected on device
    const int* batch = (const int*)d_in[2];
    const float* W1l = (const float*)d_in[3];
    const float* b1  = (const float*)d_in[4];
    const float* W1r = (const float*)d_in[5];
    const float* W2l = (const float*)d_in[6];
    const float* b2  = (const float*)d_in[7];
    const float* W2r = (const float*)d_in[8];
    const float* W3l = (const float*)d_in[9];
    const float* b3  = (const float*)d_in[10];
    const float* W3r = (const float*)d_in[11];
    const float* Wc1 = (const float*)d_in[12];
    const float* bc1 = (const float*)d_in[13];
    const float* Wc2 = (const float*)d_in[14];
    const float* bc2 = (const float*)d_in[15];
    float* out = (float*)d_out;

    const int ZB = 256;
    const int gather_blocks = (NN * 32 + 255) / 256;          // warp per node
    const int node_blocks   = (NN + TILE_N - 1) / TILE_N;     // 782

    // CSR build (4 launches)
    init_kernel<<<(NN + ZB - 1) / ZB, ZB>>>(ei, batch);
    deg_kernel<<<(NE + ZB - 1) / ZB, ZB>>>(ei);
    scan_kernel<<<SCAN_NB, SCAN_BS>>>();
    fill_kernel<<<(NE + ZB - 1) / ZB, ZB>>>(ei);

    // layer 1: x -> h0
    gather_kernel<<<gather_blocks, 256>>>(x, 0);
    node_kernel<<<node_blocks, 256>>>(x, W1l, b1, W1r, 0, 1);
    // layer 2: h0 -> h1
    gather_kernel<<<gather_blocks, 256>>>(x, 1);
    node_kernel<<<node_blocks, 256>>>(x, W2l, b2, W2r, 1, 2);
    // layer 3: h1 -> h0
    gather_kernel<<<gather_blocks, 256>>>(x, 2);
    node_kernel<<<node_blocks, 256>>>(x, W3l, b3, W3r, 2, 1);

    // pool + fused head (1 launch)
    pool_kernel<<<(NN + 255) / 256, 256>>>(batch, Wc1, bc1, Wc2, bc2, out);
}

// round 16
// speedup vs baseline: 1.0413x; 1.0413x over previous
#include <cuda_runtime.h>

#define NN 100000
#define NE 1600000
#define CH 64
#define NG 64
#define SCAN_BS 1024
#define SCAN_NB ((NN + SCAN_BS - 1) / SCAN_BS)   // 98
#define TILE_N 128                                // nodes per node-kernel block

// ---------------- device scratch (no allocation allowed) ----------------
__device__ __align__(16) float g_agg[NN * CH];
__device__ __align__(16) float g_h0[NN * CH];
__device__ __align__(16) float g_h1[NN * CH];
__device__ float g_inv[NN];
__device__ int   g_deg[NN];
__device__ int   g_off[NN];
__device__ int   g_fill[NN];
__device__ int   g_srcl[NE];
__device__ int   g_bsum[SCAN_NB];
__device__ float g_pool[NG * CH];
__device__ float g_pcnt[NG];
__device__ int   g_is64_ei;
__device__ int   g_is64_b;

__device__ __forceinline__ unsigned to_tf32(float f) {
    unsigned r;
    asm("cvt.rna.tf32.f32 %0, %1;" : "=r"(r) : "f"(f));
    return r;
}

// ---------------- init: zero deg/pool + dtype detect ----------------
// int64 little-endian with values < 2^31 => odd 32-bit words are zero.
// Probe indices are in-bounds for BOTH int32 and int64 layouts.
__global__ void init_kernel(const int* __restrict__ ei32, const int* __restrict__ b32) {
    int i = blockIdx.x * blockDim.x + threadIdx.x;
    if (i < NN) g_deg[i] = 0;
    if (blockIdx.x == 0) {
        for (int j = threadIdx.x; j < NG * CH; j += blockDim.x) g_pool[j] = 0.f;
        if (threadIdx.x < NG) g_pcnt[threadIdx.x] = 0.f;
        if (threadIdx.x == 0) {
            int oe = 0, ob = 0;
#pragma unroll 1
            for (int t = 0; t < 64; t++) oe |= ei32[2 * (t * 24999 + 7) + 1];
#pragma unroll 1
            for (int t = 0; t < 64; t++) ob |= b32[2 * (t * 780 + 3) + 1];
            g_is64_ei = (oe == 0) ? 1 : 0;
            g_is64_b  = (ob == 0) ? 1 : 0;
        }
    }
}

// ---------------- CSR build ----------------
__global__ void deg_kernel(const int* __restrict__ ei) {
    int e = blockIdx.x * blockDim.x + threadIdx.x;
    if (e < NE) {
        int d = g_is64_ei ? ei[2 * (NE + e)] : ei[NE + e];
        atomicAdd(&g_deg[d], 1);
    }
}
__global__ void scan1_kernel() {
    __shared__ int s[SCAN_BS];
    int t = threadIdx.x;
    int gid = blockIdx.x * SCAN_BS + t;
    int v = (gid < NN) ? g_deg[gid] : 0;
    s[t] = v;
    __syncthreads();
    for (int off = 1; off < SCAN_BS; off <<= 1) {
        int x = (t >= off) ? s[t - off] : 0;
        __syncthreads();
        s[t] += x;
        __syncthreads();
    }
    if (gid < NN) g_off[gid] = s[t] - v;        // exclusive within block
    if (t == SCAN_BS - 1) g_bsum[blockIdx.x] = s[t];
}
// per-block base via reduction of preceding block sums; also fills inv + fill-cursor
__global__ void scan2b_kernel() {
    __shared__ int s[128];
    __shared__ int base_s;
    int t = threadIdx.x;
    if (t < 128) s[t] = (t < (int)blockIdx.x && t < SCAN_NB) ? g_bsum[t] : 0;
    __syncthreads();
    if (t < 64) s[t] += s[t + 64];
    __syncthreads();
    if (t < 32) {
        int v = s[t] + s[t + 32];
        for (int o = 16; o > 0; o >>= 1) v += __shfl_down_sync(0xffffffffu, v, o);
        if (t == 0) base_s = v;
    }
    __syncthreads();
    int gid = blockIdx.x * SCAN_BS + t;
    if (gid < NN) {
        int o = g_off[gid] + base_s;
        g_off[gid] = o;
        g_fill[gid] = o;
        g_inv[gid] = 1.0f / fmaxf((float)g_deg[gid], 1.0f);
    }
}
__global__ void fill_kernel(const int* __restrict__ ei) {
    int e = blockIdx.x * blockDim.x + threadIdx.x;
    if (e < NE) {
        int is64 = g_is64_ei;
        int s = is64 ? ei[2 * e]        : ei[e];
        int d = is64 ? ei[2 * (NE + e)] : ei[NE + e];
        g_srcl[atomicAdd(&g_fill[d], 1)] = s;
    }
}

// ---------------- aggregation via gather: coalesced index preload + shfl broadcast ----------------
// warp per dst node; lane owns channels 2*lane, 2*lane+1 (one float2 per row).
// All <=32 neighbor indices loaded in ONE coalesced LDG (lane-parallel), then
// broadcast via shfl -> row loads have no index-load latency in their chain and
// issue back-to-back (MLP = deg). deg>32 tail uses the scalar path (rare).
__global__ void __launch_bounds__(256) gather_kernel(const float* __restrict__ Xext,
                                                     int srcsel) {
    const float* __restrict__ X = (srcsel == 0) ? Xext : (srcsel == 1 ? g_h0 : g_h1);
    int warp = (blockIdx.x * blockDim.x + threadIdx.x) >> 5;
    if (warp >= NN) return;
    int lane = threadIdx.x & 31;
    int co = lane * 2;                 // channel offset for this lane
    int beg = g_off[warp];
    int deg = g_deg[warp];

    float a0 = 0.f, a1 = 0.f;
    int dq = (deg < 32) ? deg : 32;
    // coalesced lane-parallel index load (one LDG for up to 32 indices)
    int myidx = (lane < dq) ? g_srcl[beg + lane] : 0;

    int j = 0;
#pragma unroll 1
    for (; j + 4 <= dq; j += 4) {
        int s0 = __shfl_sync(0xffffffffu, myidx, j);
        int s1 = __shfl_sync(0xffffffffu, myidx, j + 1);
        int s2 = __shfl_sync(0xffffffffu, myidx, j + 2);
        int s3 = __shfl_sync(0xffffffffu, myidx, j + 3);
        float2 v0 = *(const float2*)(X + (size_t)s0 * CH + co);
        float2 v1 = *(const float2*)(X + (size_t)s1 * CH + co);
        float2 v2 = *(const float2*)(X + (size_t)s2 * CH + co);
        float2 v3 = *(const float2*)(X + (size_t)s3 * CH + co);
        a0 += v0.x + v1.x + v2.x + v3.x;
        a1 += v0.y + v1.y + v2.y + v3.y;
    }
    for (; j < dq; j++) {
        int s0 = __shfl_sync(0xffffffffu, myidx, j);
        float2 v = *(const float2*)(X + (size_t)s0 * CH + co);
        a0 += v.x;
        a1 += v.y;
    }
    // rare tail: degree > 32
    for (; j < deg; j++) {
        float2 v = *(const float2*)(X + (size_t)g_srcl[beg + j] * CH + co);
        a0 += v.x;
        a1 += v.y;
    }
    float iv = g_inv[warp];
    *(float2*)(g_agg + (size_t)warp * CH + co) = make_float2(a0 * iv, a1 * iv);
}

// ---------------- node transform: tf32 tensor-core GEMM (R13-proven) ----------------
// Y = relu([agg | X] @ [Wl;Wr] + b) via mma.sync.m16n8k8 tf32.
// 128-node tile, 256 threads (8 warps), warp computes a 16x64 output tile.
__global__ void __launch_bounds__(256) node_kernel(const float* __restrict__ Xext,
                                                   const float* __restrict__ Wl,
                                                   const float* __restrict__ bvec,
                                                   const float* __restrict__ Wr,
                                                   int srcsel, int dstsel) {
    const float* __restrict__ Xin = (srcsel == 0) ? Xext : (srcsel == 1 ? g_h0 : g_h1);
    float* __restrict__ Yout = (dstsel == 1) ? g_h0 : g_h1;

    __shared__ __align__(16) unsigned Wt[64][132];    // 33.8 KB: Wt[n][k], k<64: Wl, else Wr
    __shared__ __align__(16) unsigned As[TILE_N][20]; // 10.2 KB: A chunk [node][16 k]
    __shared__ float bs[64];

    int tid = threadIdx.x;
    int nbase = blockIdx.x * TILE_N;
    int w = tid >> 5;          // warp 0..7: nodes 16w .. 16w+15
    int lane = tid & 31;
    int g = lane >> 2;         // 0..7
    int tq = lane & 3;         // 0..3

    // ---- stage Wt (transposed, tf32) + bias ----
    for (int i = tid; i < 64 * 64; i += 256) {
        int k = i >> 6, n = i & 63;
        Wt[n][k]      = to_tf32(Wl[i]);   // Wl[k][n]
        Wt[n][k + 64] = to_tf32(Wr[i]);
    }
    if (tid < 64) bs[tid] = bvec[tid];

    float acc[8][4];
#pragma unroll
    for (int nt = 0; nt < 8; nt++)
#pragma unroll
        for (int q = 0; q < 4; q++) acc[nt][q] = 0.f;

#pragma unroll 1
    for (int c = 0; c < 8; c++) {            // 8 chunks of 16 k; c<4: agg, else X
        __syncthreads();
        {   // stage A chunk (tf32)
            const float* __restrict__ S = (c < 4) ? g_agg : Xin;
            int koff = (c & 3) * 16;
            int k4 = (tid & 3) * 4;
            int n0 = tid >> 2;               // 0..63
#pragma unroll
            for (int nn = n0; nn < TILE_N; nn += 64) {
                int n = nbase + nn;
                float4 v = make_float4(0.f, 0.f, 0.f, 0.f);
                if (n < NN) v = *(const float4*)&S[(size_t)n * CH + koff + k4];
                As[nn][k4 + 0] = to_tf32(v.x);
                As[nn][k4 + 1] = to_tf32(v.y);
                As[nn][k4 + 2] = to_tf32(v.z);
                As[nn][k4 + 3] = to_tf32(v.w);
            }
        }
        __syncthreads();
        int kb = c * 16;                     // k base within 0..127 (Wt column)
#pragma unroll
        for (int ks = 0; ks < 2; ks++) {     // two k8 steps per chunk
            int kk = ks * 8;
            unsigned a0 = As[w * 16 + g][kk + tq];
            unsigned a1 = As[w * 16 + g + 8][kk + tq];
            unsigned a2 = As[w * 16 + g][kk + tq + 4];
            unsigned a3 = As[w * 16 + g + 8][kk + tq + 4];
#pragma unroll
            for (int nt = 0; nt < 8; nt++) {
                unsigned b0 = Wt[nt * 8 + g][kb + kk + tq];
                unsigned b1 = Wt[nt * 8 + g][kb + kk + tq + 4];
                asm volatile(
                    "mma.sync.aligned.m16n8k8.row.col.f32.tf32.tf32.f32 "
                    "{%0,%1,%2,%3}, {%4,%5,%6,%7}, {%8,%9}, {%0,%1,%2,%3};"
                    : "+f"(acc[nt][0]), "+f"(acc[nt][1]),
                      "+f"(acc[nt][2]), "+f"(acc[nt][3])
                    : "r"(a0), "r"(a1), "r"(a2), "r"(a3), "r"(b0), "r"(b1));
            }
        }
    }

    // ---- epilogue: bias + relu + store ----
    int n0 = nbase + w * 16 + g;
    int n1 = n0 + 8;
#pragma unroll
    for (int nt = 0; nt < 8; nt++) {
        int col = nt * 8 + 2 * tq;
        float b0 = bs[col], b1 = bs[col + 1];
        if (n0 < NN) {
            float2 o = make_float2(fmaxf(acc[nt][0] + b0, 0.f),
                                   fmaxf(acc[nt][1] + b1, 0.f));
            *(float2*)&Yout[(size_t)n0 * CH + col] = o;
        }
        if (n1 < NN) {
            float2 o = make_float2(fmaxf(acc[nt][2] + b0, 0.f),
                                   fmaxf(acc[nt][3] + b1, 0.f));
            *(float2*)&Yout[(size_t)n1 * CH + col] = o;
        }
    }
}

// ---------------- pooling (batch is sorted) ----------------
__global__ void __launch_bounds__(256) pool_kernel(const int* __restrict__ batch) {
    int is64 = g_is64_b;
    const float* H = g_h0;   // final layer output lives in g_h0
    int c = threadIdx.x & 63;
    int rg = threadIdx.x >> 6;
    int r0 = blockIdx.x * 256 + rg * 64;
    float acc = 0.f, cacc = 0.f;
    int cur = -1;
    for (int i = 0; i < 64; i++) {
        int r = r0 + i;
        if (r >= NN) break;
        int g = is64 ? batch[2 * r] : batch[r];
        if (g != cur) {
            if (cur >= 0) {
                atomicAdd(&g_pool[cur * CH + c], acc);
                if (c == 0) atomicAdd(&g_pcnt[cur], cacc);
            }
            cur = g; acc = 0.f; cacc = 0.f;
        }
        acc += H[(size_t)r * CH + c];
        cacc += 1.f;
    }
    if (cur >= 0) {
        atomicAdd(&g_pool[cur * CH + c], acc);
        if (c == 0) atomicAdd(&g_pcnt[cur], cacc);
    }
}

// ---------------- MLP head ----------------
__global__ void head_kernel(const float* __restrict__ Wc1, const float* __restrict__ bc1,
                            const float* __restrict__ Wc2, const float* __restrict__ bc2,
                            float* __restrict__ out) {
    int g = threadIdx.x;
    if (g >= NG) return;
    float iv = 1.0f / fmaxf(g_pcnt[g], 1.0f);
    float gv[64];
#pragma unroll
    for (int k = 0; k < 64; k++) gv[k] = g_pool[g * CH + k] * iv;
    float o0 = bc2[0], o1 = bc2[1];
    for (int j = 0; j < 32; j++) {
        float h = bc1[j];
#pragma unroll
        for (int k = 0; k < 64; k++) h += gv[k] * Wc1[k * 32 + j];
        h = fmaxf(h, 0.f);
        o0 += h * Wc2[j * 2 + 0];
        o1 += h * Wc2[j * 2 + 1];
    }
    out[g * 2 + 0] = o0;
    out[g * 2 + 1] = o1;
}

extern "C" void kernel_launch(void* const* d_in, const int* in_sizes, int n_in,
                              void* d_out, int out_size) {
    (void)in_sizes; (void)n_in; (void)out_size;
    const float* x   = (const float*)d_in[0];
    const int* ei    = (const int*)d_in[1];    // width auto-detected on device
    const int* batch = (const int*)d_in[2];
    const float* W1l = (const float*)d_in[3];
    const float* b1  = (const float*)d_in[4];
    const float* W1r = (const float*)d_in[5];
    const float* W2l = (const float*)d_in[6];
    const float* b2  = (const float*)d_in[7];
    const float* W2r = (const float*)d_in[8];
    const float* W3l = (const float*)d_in[9];
    const float* b3  = (const float*)d_in[10];
    const float* W3r = (const float*)d_in[11];
    const float* Wc1 = (const float*)d_in[12];
    const float* bc1 = (const float*)d_in[13];
    const float* Wc2 = (const float*)d_in[14];
    const float* bc2 = (const float*)d_in[15];
    float* out = (float*)d_out;

    const int ZB = 256;
    const int gather_blocks = (NN * 32 + 255) / 256;          // warp per node
    const int node_blocks   = (NN + TILE_N - 1) / TILE_N;     // 782

    // CSR build (5 launches)
    init_kernel<<<(NN + ZB - 1) / ZB, ZB>>>(ei, batch);
    deg_kernel<<<(NE + ZB - 1) / ZB, ZB>>>(ei);
    scan1_kernel<<<SCAN_NB, SCAN_BS>>>();
    scan2b_kernel<<<SCAN_NB, SCAN_BS>>>();
    fill_kernel<<<(NE + ZB - 1) / ZB, ZB>>>(ei);

    // layer 1: x -> h0
    gather_kernel<<<gather_blocks, 256>>>(x, 0);
    node_kernel<<<node_blocks, 256>>>(x, W1l, b1, W1r, 0, 1);
    // layer 2: h0 -> h1
    gather_kernel<<<gather_blocks, 256>>>(x, 1);
    node_kernel<<<node_blocks, 256>>>(x, W2l, b2, W2r, 1, 2);
    // layer 3: h1 -> h0
    gather_kernel<<<gather_blocks, 256>>>(x, 2);
    node_kernel<<<node_blocks, 256>>>(x, W3l, b3, W3r, 2, 1);

    // pool + head
    pool_kernel<<<(NN + 255) / 256, 256>>>(batch);
    head_kernel<<<1, 64>>>(Wc1, bc1, Wc2, bc2, out);
}

// round 17
// speedup vs baseline: 1.1823x; 1.1354x over previous
#include <cuda_runtime.h>

#define NN 100000
#define NE 1600000
#define CH 64
#define NG 64
#define SCAN_BS 1024
#define SCAN_NB ((NN + SCAN_BS - 1) / SCAN_BS)   // 98
#define TILE_N 128                                // nodes per node-kernel block

// ---------------- device scratch (no allocation allowed) ----------------
// NOTE: BSS zero-init is load-time; trailing cleanup in pool/head restores the
// zero-state after every execution so each graph replay sees identical state.
__device__ __align__(16) float g_agg[NN * CH];
__device__ __align__(16) float g_h0[NN * CH];
__device__ __align__(16) float g_h1[NN * CH];
__device__ float g_inv[NN];
__device__ int   g_deg[NN];
__device__ int   g_off[NN];
__device__ int   g_fill[NN];
__device__ int   g_srcl[NE];
__device__ float g_pool[NG * CH];
__device__ float g_pcnt[NG];
// lookback-scan bookkeeping (zeroed by trailing cleanup)
__device__ int   g_ticket;
__device__ int   g_status[SCAN_NB];   // 0=invalid, 1=aggregate ready, 2=prefix ready
__device__ int   g_aggv[SCAN_NB];
__device__ int   g_prefv[SCAN_NB];

__device__ __forceinline__ unsigned to_tf32(float f) {
    unsigned r;
    asm("cvt.rna.tf32.f32 %0, %1;" : "=r"(r) : "f"(f));
    return r;
}

// per-block int64-vs-int32 detect: int64 little-endian with values < 2^31 =>
// odd 32-bit words are zero. Probes in-bounds for both layouts.
__device__ __forceinline__ int detect_is64_ei(const int* __restrict__ p) {
    int o = 0;
#pragma unroll
    for (int t = 0; t < 8; t++) o |= p[2 * (t * 199999 + 7) + 1];
    return (o == 0) ? 1 : 0;
}
__device__ __forceinline__ int detect_is64_b(const int* __restrict__ p) {
    int o = 0;
#pragma unroll
    for (int t = 0; t < 8; t++) o |= p[2 * (t * 780 + 3) + 1];
    return (o == 0) ? 1 : 0;
}

// ---------------- CSR build ----------------
__global__ void deg_kernel(const int* __restrict__ ei) {
    __shared__ int sh64;
    if (threadIdx.x == 0) sh64 = detect_is64_ei(ei);
    __syncthreads();
    int is64 = sh64;
    int e = blockIdx.x * blockDim.x + threadIdx.x;
    if (e < NE) {
        int d = is64 ? ei[2 * (NE + e)] : ei[NE + e];
        atomicAdd(&g_deg[d], 1);
    }
}

// single-pass decoupled-lookback exclusive scan of g_deg -> g_off (+ fill cursor + inv)
__global__ void scan_kernel() {
    __shared__ int s[SCAN_BS];
    __shared__ int sh_bid;
    __shared__ int sh_base;
    int t = threadIdx.x;

    if (t == 0) sh_bid = atomicAdd(&g_ticket, 1);
    __syncthreads();
    int bid = sh_bid;

    int gid = bid * SCAN_BS + t;
    int v = (gid < NN) ? g_deg[gid] : 0;
    s[t] = v;
    __syncthreads();
    for (int off = 1; off < SCAN_BS; off <<= 1) {
        int x = (t >= off) ? s[t - off] : 0;
        __syncthreads();
        s[t] += x;
        __syncthreads();
    }
    int total = s[SCAN_BS - 1];

    if (t == 0) {
        if (bid == 0) {
            g_prefv[0] = total;
            __threadfence();
            ((volatile int*)g_status)[0] = 2;
            sh_base = 0;
        } else {
            g_aggv[bid] = total;
            __threadfence();
            ((volatile int*)g_status)[bid] = 1;
            int base = 0;
            int p = bid - 1;
            while (p >= 0) {
                int st;
                do { st = ((volatile int*)g_status)[p]; } while (st == 0);
                __threadfence();
                if (st == 2) { base += g_prefv[p]; break; }
                base += g_aggv[p];
                p--;
            }
            g_prefv[bid] = base + total;
            __threadfence();
            ((volatile int*)g_status)[bid] = 2;
            sh_base = base;
        }
    }
    __syncthreads();
    int base = sh_base;

    if (gid < NN) {
        int o = base + s[t] - v;     // exclusive prefix
        g_off[gid]  = o;
        g_fill[gid] = o;
        g_inv[gid]  = 1.0f / fmaxf((float)g_deg[gid], 1.0f);
    }
}

__global__ void fill_kernel(const int* __restrict__ ei) {
    __shared__ int sh64;
    if (threadIdx.x == 0) sh64 = detect_is64_ei(ei);
    __syncthreads();
    int is64 = sh64;
    int e = blockIdx.x * blockDim.x + threadIdx.x;
    if (e < NE) {
        int s = is64 ? ei[2 * e]        : ei[e];
        int d = is64 ? ei[2 * (NE + e)] : ei[NE + e];
        g_srcl[atomicAdd(&g_fill[d], 1)] = s;
    }
}

// ---------------- aggregation via gather (champion: LDG.64 lanes + 4-edge unroll) ----------------
__global__ void __launch_bounds__(256) gather_kernel(const float* __restrict__ Xext,
                                                     int srcsel) {
    const float* __restrict__ X = (srcsel == 0) ? Xext : (srcsel == 1 ? g_h0 : g_h1);
    int warp = (blockIdx.x * blockDim.x + threadIdx.x) >> 5;
    if (warp >= NN) return;
    int lane = threadIdx.x & 31;
    int co = lane * 2;                 // channel offset for this lane
    int beg = g_off[warp];
    int deg = g_deg[warp];

    float a0 = 0.f, a1 = 0.f;
    int j = 0;
    for (; j + 4 <= deg; j += 4) {
        int s0 = g_srcl[beg + j];
        int s1 = g_srcl[beg + j + 1];
        int s2 = g_srcl[beg + j + 2];
        int s3 = g_srcl[beg + j + 3];
        float2 v0 = *(const float2*)(X + (size_t)s0 * CH + co);
        float2 v1 = *(const float2*)(X + (size_t)s1 * CH + co);
        float2 v2 = *(const float2*)(X + (size_t)s2 * CH + co);
        float2 v3 = *(const float2*)(X + (size_t)s3 * CH + co);
        a0 += v0.x + v1.x + v2.x + v3.x;
        a1 += v0.y + v1.y + v2.y + v3.y;
    }
    for (; j < deg; j++) {
        float2 v = *(const float2*)(X + (size_t)g_srcl[beg + j] * CH + co);
        a0 += v.x;
        a1 += v.y;
    }
    float iv = g_inv[warp];
    *(float2*)(g_agg + (size_t)warp * CH + co) = make_float2(a0 * iv, a1 * iv);
}

// ---------------- node transform: tf32 tensor-core GEMM (R13-proven) ----------------
__global__ void __launch_bounds__(256) node_kernel(const float* __restrict__ Xext,
                                                   const float* __restrict__ Wl,
                                                   const float* __restrict__ bvec,
                                                   const float* __restrict__ Wr,
                                                   int srcsel, int dstsel) {
    const float* __restrict__ Xin = (srcsel == 0) ? Xext : (srcsel == 1 ? g_h0 : g_h1);
    float* __restrict__ Yout = (dstsel == 1) ? g_h0 : g_h1;

    __shared__ __align__(16) unsigned Wt[64][132];    // 33.8 KB: Wt[n][k], k<64: Wl, else Wr
    __shared__ __align__(16) unsigned As[TILE_N][20]; // 10.2 KB: A chunk [node][16 k]
    __shared__ float bs[64];

    int tid = threadIdx.x;
    int nbase = blockIdx.x * TILE_N;
    int w = tid >> 5;          // warp 0..7: nodes 16w .. 16w+15
    int lane = tid & 31;
    int g = lane >> 2;         // 0..7
    int tq = lane & 3;         // 0..3

    for (int i = tid; i < 64 * 64; i += 256) {
        int k = i >> 6, n = i & 63;
        Wt[n][k]      = to_tf32(Wl[i]);   // Wl[k][n]
        Wt[n][k + 64] = to_tf32(Wr[i]);
    }
    if (tid < 64) bs[tid] = bvec[tid];

    float acc[8][4];
#pragma unroll
    for (int nt = 0; nt < 8; nt++)
#pragma unroll
        for (int q = 0; q < 4; q++) acc[nt][q] = 0.f;

#pragma unroll 1
    for (int c = 0; c < 8; c++) {            // 8 chunks of 16 k; c<4: agg, else X
        __syncthreads();
        {
            const float* __restrict__ S = (c < 4) ? g_agg : Xin;
            int koff = (c & 3) * 16;
            int k4 = (tid & 3) * 4;
            int n0 = tid >> 2;               // 0..63
#pragma unroll
            for (int nn = n0; nn < TILE_N; nn += 64) {
                int n = nbase + nn;
                float4 v = make_float4(0.f, 0.f, 0.f, 0.f);
                if (n < NN) v = *(const float4*)&S[(size_t)n * CH + koff + k4];
                As[nn][k4 + 0] = to_tf32(v.x);
                As[nn][k4 + 1] = to_tf32(v.y);
                As[nn][k4 + 2] = to_tf32(v.z);
                As[nn][k4 + 3] = to_tf32(v.w);
            }
        }
        __syncthreads();
        int kb = c * 16;
#pragma unroll
        for (int ks = 0; ks < 2; ks++) {
            int kk = ks * 8;
            unsigned a0 = As[w * 16 + g][kk + tq];
            unsigned a1 = As[w * 16 + g + 8][kk + tq];
            unsigned a2 = As[w * 16 + g][kk + tq + 4];
            unsigned a3 = As[w * 16 + g + 8][kk + tq + 4];
#pragma unroll
            for (int nt = 0; nt < 8; nt++) {
                unsigned b0 = Wt[nt * 8 + g][kb + kk + tq];
                unsigned b1 = Wt[nt * 8 + g][kb + kk + tq + 4];
                asm volatile(
                    "mma.sync.aligned.m16n8k8.row.col.f32.tf32.tf32.f32 "
                    "{%0,%1,%2,%3}, {%4,%5,%6,%7}, {%8,%9}, {%0,%1,%2,%3};"
                    : "+f"(acc[nt][0]), "+f"(acc[nt][1]),
                      "+f"(acc[nt][2]), "+f"(acc[nt][3])
                    : "r"(a0), "r"(a1), "r"(a2), "r"(a3), "r"(b0), "r"(b1));
            }
        }
    }

    int n0 = nbase + w * 16 + g;
    int n1 = n0 + 8;
#pragma unroll
    for (int nt = 0; nt < 8; nt++) {
        int col = nt * 8 + 2 * tq;
        float b0 = bs[col], b1 = bs[col + 1];
        if (n0 < NN) {
            float2 o = make_float2(fmaxf(acc[nt][0] + b0, 0.f),
                                   fmaxf(acc[nt][1] + b1, 0.f));
            *(float2*)&Yout[(size_t)n0 * CH + col] = o;
        }
        if (n1 < NN) {
            float2 o = make_float2(fmaxf(acc[nt][2] + b0, 0.f),
                                   fmaxf(acc[nt][3] + b1, 0.f));
            *(float2*)&Yout[(size_t)n1 * CH + col] = o;
        }
    }
}

// ---------------- pooling (batch is sorted) + trailing cleanup ----------------
__global__ void __launch_bounds__(256) pool_kernel(const int* __restrict__ batch) {
    __shared__ int sh64;
    if (threadIdx.x == 0) sh64 = detect_is64_b(batch);
    __syncthreads();
    int is64 = sh64;
    const float* H = g_h0;   // final layer output lives in g_h0
    int c = threadIdx.x & 63;
    int rg = threadIdx.x >> 6;
    int r0 = blockIdx.x * 256 + rg * 64;
    float acc = 0.f, cacc = 0.f;
    int cur = -1;
    for (int i = 0; i < 64; i++) {
        int r = r0 + i;
        if (r >= NN) break;
        int g = is64 ? batch[2 * r] : batch[r];
        if (g != cur) {
            if (cur >= 0) {
                atomicAdd(&g_pool[cur * CH + c], acc);
                if (c == 0) atomicAdd(&g_pcnt[cur], cacc);
            }
            cur = g; acc = 0.f; cacc = 0.f;
        }
        acc += H[(size_t)r * CH + c];
        cacc += 1.f;
    }
    if (cur >= 0) {
        atomicAdd(&g_pool[cur * CH + c], acc);
        if (c == 0) atomicAdd(&g_pcnt[cur], cacc);
    }

    // trailing cleanup for next replay: zero g_deg + scan bookkeeping
    int gid = blockIdx.x * blockDim.x + threadIdx.x;
    if (gid < NN) g_deg[gid] = 0;
    if (gid < SCAN_NB) g_status[gid] = 0;
    if (gid == 0) g_ticket = 0;
}

// ---------------- MLP head (+ trailing cleanup of pool accumulators) ----------------
__global__ void __launch_bounds__(256) head_kernel(const float* __restrict__ Wc1,
                                                   const float* __restrict__ bc1,
                                                   const float* __restrict__ Wc2,
                                                   const float* __restrict__ bc2,
                                                   float* __restrict__ out) {
    int g = threadIdx.x;
    if (g < NG) {
        float iv = 1.0f / fmaxf(g_pcnt[g], 1.0f);
        float gv[64];
#pragma unroll
        for (int k = 0; k < 64; k++) gv[k] = g_pool[g * CH + k] * iv;
        float o0 = bc2[0], o1 = bc2[1];
        for (int j = 0; j < 32; j++) {
            float h = bc1[j];
#pragma unroll
            for (int k = 0; k < 64; k++) h += gv[k] * Wc1[k * 32 + j];
            h = fmaxf(h, 0.f);
            o0 += h * Wc2[j * 2 + 0];
            o1 += h * Wc2[j * 2 + 1];
        }
        out[g * 2 + 0] = o0;
        out[g * 2 + 1] = o1;
    }
    __syncthreads();   // all reads of g_pool/g_pcnt done
    for (int i = threadIdx.x; i < NG * CH; i += blockDim.x) g_pool[i] = 0.f;
    if (threadIdx.x < NG) g_pcnt[threadIdx.x] = 0.f;
}

extern "C" void kernel_launch(void* const* d_in, const int* in_sizes, int n_in,
                              void* d_out, int out_size) {
    (void)in_sizes; (void)n_in; (void)out_size;
    const float* x   = (const float*)d_in[0];
    const int* ei    = (const int*)d_in[1];    // width auto-detected per block
    const int* batch = (const int*)d_in[2];
    const float* W1l = (const float*)d_in[3];
    const float* b1  = (const float*)d_in[4];
    const float* W1r = (const float*)d_in[5];
    const float* W2l = (const float*)d_in[6];
    const float* b2  = (const float*)d_in[7];
    const float* W2r = (const float*)d_in[8];
    const float* W3l = (const float*)d_in[9];
    const float* b3  = (const float*)d_in[10];
    const float* W3r = (const float*)d_in[11];
    const float* Wc1 = (const float*)d_in[12];
    const float* bc1 = (const float*)d_in[13];
    const float* Wc2 = (const float*)d_in[14];
    const float* bc2 = (const float*)d_in[15];
    float* out = (float*)d_out;

    const int ZB = 256;
    const int gather_blocks = (NN * 32 + 255) / 256;          // warp per node
    const int node_blocks   = (NN + TILE_N - 1) / TILE_N;     // 782

    // CSR build (3 launches; state pre-zeroed by BSS init / trailing cleanup)
    deg_kernel<<<(NE + ZB - 1) / ZB, ZB>>>(ei);
    scan_kernel<<<SCAN_NB, SCAN_BS>>>();
    fill_kernel<<<(NE + ZB - 1) / ZB, ZB>>>(ei);

    // layer 1: x -> h0   (gather is launch #4 -> ncu's capture slot)
    gather_kernel<<<gather_blocks, 256>>>(x, 0);
    node_kernel<<<node_blocks, 256>>>(x, W1l, b1, W1r, 0, 1);
    // layer 2: h0 -> h1
    gather_kernel<<<gather_blocks, 256>>>(x, 1);
    node_kernel<<<node_blocks, 256>>>(x, W2l, b2, W2r, 1, 2);
    // layer 3: h1 -> h0
    gather_kernel<<<gather_blocks, 256>>>(x, 2);
    node_kernel<<<node_blocks, 256>>>(x, W3l, b3, W3r, 2, 1);

    // pool + head (with trailing cleanup for next replay)
    pool_kernel<<<(NN + 255) / 256, 256>>>(batch);
    head_kernel<<<1, 256>>>(Wc1, bc1, Wc2, bc2, out);
}